// round 11
// baseline (speedup 1.0000x reference)
#include <cuda_runtime.h>
#include <cuda_bf16.h>
#include <math.h>
#include <cstdint>

#define DIMF 512
#define DH 64
#define MLM 256
#define BATCH 4
#define SEQ 4096
#define TOK (BATCH*SEQ)
#define LRED (SEQ/MLM)
#define PITERS 6
#define QSCALE 0.125f
#define KSZ 33
#define EPSLN 1e-5f
#define QKVW 192
#define PINV_CTAS 64

// ---------------- scratch (device globals; no runtime allocation) ------------
__device__ float g_qkv[TOK*QKVW];
__device__ float g_ql[BATCH*MLM*DH];
__device__ float g_kl[BATCH*MLM*DH];
__device__ float g_a2[BATCH*MLM*MLM];
__device__ float g_z[BATCH*MLM*MLM];
__device__ float g_z2[BATCH*MLM*MLM];
__device__ float g_xz[BATCH*MLM*MLM];
__device__ float g_t2[BATCH*MLM*MLM];
__device__ float g_t4[BATCH*MLM*MLM];
__device__ float g_a3v[BATCH*MLM*DH];
__device__ float g_cv[TOK*DH];
__device__ unsigned int g_cmax;
__device__ unsigned int g_rmax;
__device__ unsigned int g_bar;
// bf16 operands
__device__ __nv_bfloat16 g_xnb[TOK*DIMF];
__device__ __nv_bfloat16 g_wqkvTb[QKVW*DIMF];
__device__ __nv_bfloat16 g_woutTb[DIMF*DH];
__device__ __nv_bfloat16 g_qkvb[TOK*QKVW];
__device__ __nv_bfloat16 g_qlb[BATCH*MLM*DH];
__device__ __nv_bfloat16 g_klb[BATCH*MLM*DH];
__device__ __nv_bfloat16 g_a1b[(size_t)BATCH*SEQ*MLM];
__device__ __nv_bfloat16 g_zb[BATCH*MLM*MLM];
__device__ __nv_bfloat16 g_leftb[(size_t)BATCH*SEQ*MLM];
__device__ __nv_bfloat16 g_a3b[(size_t)BATCH*MLM*SEQ];
__device__ __nv_bfloat16 g_a3vTb[BATCH*DH*MLM];
__device__ __nv_bfloat16 g_ohb[TOK*DH];

__device__ __forceinline__ uint32_t smem_u32(const void* p) {
    uint32_t a;
    asm("{ .reg .u64 t; cvta.to.shared.u64 t, %1; cvt.u32.u64 %0, t; }" : "=r"(a) : "l"(p));
    return a;
}
__device__ __forceinline__ void cp_async16(uint32_t dst, const void* src) {
    asm volatile("cp.async.cg.shared.global [%0], [%1], 16;" :: "r"(dst), "l"(src));
}
__device__ __forceinline__ float tf32r(float v) {
    uint32_t u;
    asm("cvt.rna.tf32.f32 %0, %1;" : "=r"(u) : "f"(v));
    return __uint_as_float(u);
}

// =============== pipelined bf16 HMMA GEMM (128 x BN x 64) =====================
// C[M,N] = A[M,K] @ B^T.  TB=false: B [N,K]; TB=true: B [K,N] via ldmatrix.trans.
// OM: 0 = fp32 out, 1 = fp32 + bf16 mirror, 2 = bf16 only,
//     3 = fp32 out: C = acc + D + bias,  4 = bf16 only: C2 = bf16(acc + D).
template<int BN, int OM, bool TB>
__global__ void __launch_bounds__(256) hgemm_tt(
    const __nv_bfloat16* __restrict__ A, const __nv_bfloat16* __restrict__ B,
    float* __restrict__ C, __nv_bfloat16* __restrict__ C2,
    const float* __restrict__ Dp, const float* __restrict__ biasp,
    int K, int lda, int ldb, int ldc,
    long long bsA, long long bsB, long long bsC)
{
    constexpr int NJ = BN / 32;
    __shared__ __align__(16) char sA[2][128*128];
    __shared__ __align__(16) char sB[2][BN*128];
    const int tid = threadIdx.x, lane = tid & 31, w = tid >> 5;
    const int wm = (w & 3) * 32, wn = (w >> 2) * (BN/2);
    const int m0 = blockIdx.y * 128, n0 = blockIdx.x * BN, bz = blockIdx.z;
    const __nv_bfloat16* Ag = A + (long long)bz*bsA + (size_t)m0*lda;
    const __nv_bfloat16* Bg = B + (long long)bz*bsB + (TB ? (size_t)n0 : (size_t)n0*ldb);
    const uint32_t sAu = smem_u32(sA), sBu = smem_u32(sB);

    float acc[2][NJ*2][4];
#pragma unroll
    for (int i = 0; i < 2; i++)
#pragma unroll
      for (int j = 0; j < NJ*2; j++)
#pragma unroll
        for (int t = 0; t < 4; t++) acc[i][j][t] = 0.f;

    const int sub = lane >> 3, rr = lane & 7;
    const int lrow = ((sub & 1) << 3) + rr;
    const int lcbb = (sub >> 1) << 4;

    auto loadTiles = [&](int buf, int kt) {
#pragma unroll
        for (int t = 0; t < 4; t++) {
            int idx = tid + t*256, r = idx >> 3, q = idx & 7;
            cp_async16(sAu + buf*16384 + r*128 + ((q*16) ^ ((r & 7) << 4)),
                       Ag + (size_t)r*lda + kt*64 + q*8);
        }
#pragma unroll
        for (int t = 0; t < BN/32; t++) {
            int idx = tid + t*256;
            if (TB) {
                constexpr int CH = BN/8;
                int r = idx / CH, q = idx % CH;
                cp_async16(sBu + buf*(BN*128) + r*(BN*2) + ((q*16) ^ ((r & 7) << 4)),
                           Bg + (size_t)(kt*64 + r)*ldb + q*8);
            } else {
                int r = idx >> 3, q = idx & 7;
                cp_async16(sBu + buf*(BN*128) + r*128 + ((q*16) ^ ((r & 7) << 4)),
                           Bg + (size_t)r*ldb + kt*64 + q*8);
            }
        }
        asm volatile("cp.async.commit_group;");
    };

    const int nt = K >> 6;
    loadTiles(0, 0);
    for (int kt = 0; kt < nt; kt++) {
        if (kt + 1 < nt) {
            loadTiles((kt+1) & 1, kt+1);
            asm volatile("cp.async.wait_group 1;");
        } else {
            asm volatile("cp.async.wait_group 0;");
        }
        __syncthreads();
        const uint32_t aB = sAu + (kt & 1)*16384;
        const uint32_t bB = sBu + (kt & 1)*(BN*128);
#pragma unroll
        for (int ks = 0; ks < 4; ks++) {
            uint32_t a[2][4], b[NJ][4];
            const int lcb = ks*32 + lcbb;
#pragma unroll
            for (int mi = 0; mi < 2; mi++) {
                int r = wm + mi*16 + lrow;
                uint32_t ad = aB + r*128 + (lcb ^ ((r & 7) << 4));
                asm volatile("ldmatrix.sync.aligned.m8n8.x4.shared.b16 {%0,%1,%2,%3}, [%4];"
                  : "=r"(a[mi][0]),"=r"(a[mi][1]),"=r"(a[mi][2]),"=r"(a[mi][3]) : "r"(ad));
            }
#pragma unroll
            for (int nj = 0; nj < NJ; nj++) {
                if (TB) {
                    int row = ks*16 + (lane & 15);
                    int bc  = (wn + nj*16 + (lane >> 4)*8) * 2;
                    uint32_t bd = bB + row*(BN*2) + (bc ^ ((row & 7) << 4));
                    asm volatile("ldmatrix.sync.aligned.m8n8.x4.trans.shared.b16 {%0,%1,%2,%3}, [%4];"
                      : "=r"(b[nj][0]),"=r"(b[nj][1]),"=r"(b[nj][2]),"=r"(b[nj][3]) : "r"(bd));
                } else {
                    int r = wn + nj*16 + lrow;
                    uint32_t bd = bB + r*128 + (lcb ^ ((r & 7) << 4));
                    asm volatile("ldmatrix.sync.aligned.m8n8.x4.shared.b16 {%0,%1,%2,%3}, [%4];"
                      : "=r"(b[nj][0]),"=r"(b[nj][1]),"=r"(b[nj][2]),"=r"(b[nj][3]) : "r"(bd));
                }
            }
#pragma unroll
            for (int mi = 0; mi < 2; mi++)
#pragma unroll
              for (int nj = 0; nj < NJ; nj++)
#pragma unroll
                for (int s = 0; s < 2; s++) {
                    float* c = acc[mi][nj*2+s];
                    uint32_t b0 = TB ? b[nj][2*s]   : b[nj][s];
                    uint32_t b1 = TB ? b[nj][2*s+1] : b[nj][s+2];
                    asm volatile("mma.sync.aligned.m16n8k16.row.col.f32.bf16.bf16.f32 "
                        "{%0,%1,%2,%3}, {%4,%5,%6,%7}, {%8,%9}, {%0,%1,%2,%3};"
                        : "+f"(c[0]),"+f"(c[1]),"+f"(c[2]),"+f"(c[3])
                        : "r"(a[mi][0]),"r"(a[mi][1]),"r"(a[mi][2]),"r"(a[mi][3]),
                          "r"(b0),"r"(b1));
                }
        }
        __syncthreads();
    }
    float* Cg = (OM == 0 || OM == 1 || OM == 3) ? C + (long long)bz*bsC + (size_t)m0*ldc + n0 : nullptr;
    __nv_bfloat16* Cg2 = (OM == 1 || OM == 2 || OM == 4) ? C2 + (long long)bz*bsC + (size_t)m0*ldc + n0 : nullptr;
    const float* Dg = (OM == 3 || OM == 4) ? Dp + (long long)bz*bsC + (size_t)m0*ldc + n0 : nullptr;
    const int lr = lane >> 2, lc = lane & 3;
#pragma unroll
    for (int mi = 0; mi < 2; mi++)
#pragma unroll
      for (int ns = 0; ns < NJ*2; ns++) {
          size_t off = (size_t)(wm + mi*16 + lr)*ldc + wn + ns*8 + lc*2;
          float v0 = acc[mi][ns][0], v1 = acc[mi][ns][1];
          float v2 = acc[mi][ns][2], v3 = acc[mi][ns][3];
          if (OM == 3 || OM == 4) {
              float2 d0 = *(const float2*)(Dg + off);
              float2 d1 = *(const float2*)(Dg + off + 8*ldc);
              v0 += d0.x; v1 += d0.y; v2 += d1.x; v3 += d1.y;
              if (OM == 3) {
                  int col = n0 + wn + ns*8 + lc*2;
                  float b0 = biasp[col], b1 = biasp[col+1];
                  v0 += b0; v1 += b1; v2 += b0; v3 += b1;
              }
          }
          if (OM == 0 || OM == 1 || OM == 3) {
              float* p = Cg + off;
              *(float2*)p = make_float2(v0, v1);
              *(float2*)(p + 8*ldc) = make_float2(v2, v3);
          }
          if (OM == 1 || OM == 2 || OM == 4) {
              *(__nv_bfloat162*)(Cg2 + off) = __floats2bfloat162_rn(v0, v1);
              *(__nv_bfloat162*)(Cg2 + off + 8*ldc) = __floats2bfloat162_rn(v2, v3);
          }
      }
}

// =============== wide-tile HMMA GEMM: 128 x 256 x 64, dynamic smem ============
// Same math; warp tile 32x128; OM: 0 fp32 out, 2 bf16 only. TB as above.
template<int OM, bool TB>
__global__ void __launch_bounds__(256) hgemm_wide(
    const __nv_bfloat16* __restrict__ A, const __nv_bfloat16* __restrict__ B,
    float* __restrict__ C, __nv_bfloat16* __restrict__ C2,
    int K, int lda, int ldb, int ldc,
    long long bsA, long long bsB, long long bsC)
{
    constexpr int BN = 256, NJ = 8;
    extern __shared__ __align__(16) char smw[];
    const uint32_t sAu = smem_u32(smw);            // 2 x 16384
    const uint32_t sBu = sAu + 32768;              // 2 x 32768
    const int tid = threadIdx.x, lane = tid & 31, w = tid >> 5;
    const int wm = (w & 3) * 32, wn = (w >> 2) * 128;
    const int m0 = blockIdx.y * 128, n0 = blockIdx.x * BN, bz = blockIdx.z;
    const __nv_bfloat16* Ag = A + (long long)bz*bsA + (size_t)m0*lda;
    const __nv_bfloat16* Bg = B + (long long)bz*bsB + (TB ? (size_t)n0 : (size_t)n0*ldb);

    float acc[2][16][4];
#pragma unroll
    for (int i = 0; i < 2; i++)
#pragma unroll
      for (int j = 0; j < 16; j++)
#pragma unroll
        for (int t = 0; t < 4; t++) acc[i][j][t] = 0.f;

    const int sub = lane >> 3, rr = lane & 7;
    const int lrow = ((sub & 1) << 3) + rr;
    const int lcbb = (sub >> 1) << 4;

    auto loadTiles = [&](int buf, int kt) {
#pragma unroll
        for (int t = 0; t < 4; t++) {
            int idx = tid + t*256, r = idx >> 3, q = idx & 7;
            cp_async16(sAu + buf*16384 + r*128 + ((q*16) ^ ((r & 7) << 4)),
                       Ag + (size_t)r*lda + kt*64 + q*8);
        }
#pragma unroll
        for (int t = 0; t < 8; t++) {
            int idx = tid + t*256;
            if (TB) {
                int r = idx >> 5, q = idx & 31;       // 64 k-rows x 32 chunks
                cp_async16(sBu + buf*32768 + r*512 + ((q*16) ^ ((r & 7) << 4)),
                           Bg + (size_t)(kt*64 + r)*ldb + q*8);
            } else {
                int r = idx >> 3, q = idx & 7;        // 256 n-rows x 8 chunks
                cp_async16(sBu + buf*32768 + r*128 + ((q*16) ^ ((r & 7) << 4)),
                           Bg + (size_t)r*ldb + kt*64 + q*8);
            }
        }
        asm volatile("cp.async.commit_group;");
    };

    const int nt = K >> 6;
    loadTiles(0, 0);
    for (int kt = 0; kt < nt; kt++) {
        if (kt + 1 < nt) {
            loadTiles((kt+1) & 1, kt+1);
            asm volatile("cp.async.wait_group 1;");
        } else {
            asm volatile("cp.async.wait_group 0;");
        }
        __syncthreads();
        const uint32_t aB = sAu + (kt & 1)*16384;
        const uint32_t bB = sBu + (kt & 1)*32768;
#pragma unroll
        for (int ks = 0; ks < 4; ks++) {
            uint32_t a[2][4], b[NJ][4];
            const int lcb = ks*32 + lcbb;
#pragma unroll
            for (int mi = 0; mi < 2; mi++) {
                int r = wm + mi*16 + lrow;
                uint32_t ad = aB + r*128 + (lcb ^ ((r & 7) << 4));
                asm volatile("ldmatrix.sync.aligned.m8n8.x4.shared.b16 {%0,%1,%2,%3}, [%4];"
                  : "=r"(a[mi][0]),"=r"(a[mi][1]),"=r"(a[mi][2]),"=r"(a[mi][3]) : "r"(ad));
            }
#pragma unroll
            for (int nj = 0; nj < NJ; nj++) {
                if (TB) {
                    int row = ks*16 + (lane & 15);
                    int bc  = (wn + nj*16 + (lane >> 4)*8) * 2;
                    uint32_t bd = bB + row*512 + (bc ^ ((row & 7) << 4));
                    asm volatile("ldmatrix.sync.aligned.m8n8.x4.trans.shared.b16 {%0,%1,%2,%3}, [%4];"
                      : "=r"(b[nj][0]),"=r"(b[nj][1]),"=r"(b[nj][2]),"=r"(b[nj][3]) : "r"(bd));
                } else {
                    int r = wn + nj*16 + lrow;
                    uint32_t bd = bB + r*128 + (lcb ^ ((r & 7) << 4));
                    asm volatile("ldmatrix.sync.aligned.m8n8.x4.shared.b16 {%0,%1,%2,%3}, [%4];"
                      : "=r"(b[nj][0]),"=r"(b[nj][1]),"=r"(b[nj][2]),"=r"(b[nj][3]) : "r"(bd));
                }
            }
#pragma unroll
            for (int mi = 0; mi < 2; mi++)
#pragma unroll
              for (int nj = 0; nj < NJ; nj++)
#pragma unroll
                for (int s = 0; s < 2; s++) {
                    float* c = acc[mi][nj*2+s];
                    uint32_t b0 = TB ? b[nj][2*s]   : b[nj][s];
                    uint32_t b1 = TB ? b[nj][2*s+1] : b[nj][s+2];
                    asm volatile("mma.sync.aligned.m16n8k16.row.col.f32.bf16.bf16.f32 "
                        "{%0,%1,%2,%3}, {%4,%5,%6,%7}, {%8,%9}, {%0,%1,%2,%3};"
                        : "+f"(c[0]),"+f"(c[1]),"+f"(c[2]),"+f"(c[3])
                        : "r"(a[mi][0]),"r"(a[mi][1]),"r"(a[mi][2]),"r"(a[mi][3]),
                          "r"(b0),"r"(b1));
                }
        }
        __syncthreads();
    }
    float* Cg = (OM == 0) ? C + (long long)bz*bsC + (size_t)m0*ldc + n0 : nullptr;
    __nv_bfloat16* Cg2 = (OM == 2) ? C2 + (long long)bz*bsC + (size_t)m0*ldc + n0 : nullptr;
    const int lr = lane >> 2, lc = lane & 3;
#pragma unroll
    for (int mi = 0; mi < 2; mi++)
#pragma unroll
      for (int ns = 0; ns < 16; ns++) {
          size_t off = (size_t)(wm + mi*16 + lr)*ldc + wn + ns*8 + lc*2;
          if (OM == 0) {
              float* p = Cg + off;
              *(float2*)p = make_float2(acc[mi][ns][0], acc[mi][ns][1]);
              *(float2*)(p + 8*ldc) = make_float2(acc[mi][ns][2], acc[mi][ns][3]);
          } else {
              *(__nv_bfloat162*)(Cg2 + off) =
                  __floats2bfloat162_rn(acc[mi][ns][0], acc[mi][ns][1]);
              *(__nv_bfloat162*)(Cg2 + off + 8*ldc) =
                  __floats2bfloat162_rn(acc[mi][ns][2], acc[mi][ns][3]);
          }
      }
}

// =============== fused persistent pinv (init + tf32 tiles + grid barrier) =====
__device__ __forceinline__ void tf32_tile(
    const float* __restrict__ Ab, const float* __restrict__ Bb,
    const float* __restrict__ Db, float* __restrict__ Cb,
    float alpha, float beta, int m0, int n0,
    float (*As)[36], float (*Bs)[68])
{
    const int tid = threadIdx.x, lane = tid & 31, w = tid >> 5;
    const int wm = (w & 1) * 32, wn = (w >> 1) * 32;
    const int g = lane >> 2, t = lane & 3;

    float acc[2][4][4] = {};
    for (int k0 = 0; k0 < MLM; k0 += 32) {
#pragma unroll
        for (int i = 0; i < 4; i++) {
            int idx = tid + i*128;
            {
                int r = idx >> 3, c4 = (idx & 7) * 4;
                float4 f = *(const float4*)&Ab[(size_t)(m0+r)*MLM + k0 + c4];
                As[r][c4+0] = tf32r(f.x); As[r][c4+1] = tf32r(f.y);
                As[r][c4+2] = tf32r(f.z); As[r][c4+3] = tf32r(f.w);
            }
            {
                int r = idx >> 4, c4 = (idx & 15) * 4;
                float4 f = *(const float4*)&Bb[(size_t)(k0+r)*MLM + n0 + c4];
                Bs[r][c4+0] = tf32r(f.x); Bs[r][c4+1] = tf32r(f.y);
                Bs[r][c4+2] = tf32r(f.z); Bs[r][c4+3] = tf32r(f.w);
            }
        }
        __syncthreads();
#pragma unroll
        for (int kk = 0; kk < 32; kk += 8) {
            uint32_t a[2][4], b[4][2];
#pragma unroll
            for (int mi = 0; mi < 2; mi++) {
                int r = wm + mi*16 + g;
                a[mi][0] = __float_as_uint(As[r][kk+t]);
                a[mi][1] = __float_as_uint(As[r+8][kk+t]);
                a[mi][2] = __float_as_uint(As[r][kk+t+4]);
                a[mi][3] = __float_as_uint(As[r+8][kk+t+4]);
            }
#pragma unroll
            for (int nj = 0; nj < 4; nj++) {
                int cN = wn + nj*8 + g;
                b[nj][0] = __float_as_uint(Bs[kk+t][cN]);
                b[nj][1] = __float_as_uint(Bs[kk+t+4][cN]);
            }
#pragma unroll
            for (int mi = 0; mi < 2; mi++)
#pragma unroll
              for (int nj = 0; nj < 4; nj++) {
                  float* c = acc[mi][nj];
                  asm volatile("mma.sync.aligned.m16n8k8.row.col.f32.tf32.tf32.f32 "
                      "{%0,%1,%2,%3}, {%4,%5,%6,%7}, {%8,%9}, {%0,%1,%2,%3};"
                      : "+f"(c[0]),"+f"(c[1]),"+f"(c[2]),"+f"(c[3])
                      : "r"(a[mi][0]),"r"(a[mi][1]),"r"(a[mi][2]),"r"(a[mi][3]),
                        "r"(b[nj][0]),"r"(b[nj][1]));
              }
        }
        __syncthreads();
    }
#pragma unroll
    for (int mi = 0; mi < 2; mi++)
#pragma unroll
      for (int nj = 0; nj < 4; nj++) {
          int r0 = m0 + wm + mi*16 + g;
          int c0 = n0 + wn + nj*8 + t*2;
          float* c = acc[mi][nj];
          float2 v0 = make_float2(alpha*c[0], alpha*c[1]);
          float2 v1 = make_float2(alpha*c[2], alpha*c[3]);
          if (Db) {
              float2 d0 = *(const float2*)&Db[(size_t)r0*MLM + c0];
              float2 d1 = *(const float2*)&Db[(size_t)(r0+8)*MLM + c0];
              v0.x += beta*d0.x; v0.y += beta*d0.y;
              v1.x += beta*d1.x; v1.y += beta*d1.y;
          }
          *(float2*)&Cb[(size_t)r0*MLM + c0] = v0;
          *(float2*)&Cb[(size_t)(r0+8)*MLM + c0] = v1;
      }
}

__device__ __forceinline__ void grid_bar(unsigned int goal)
{
    __syncthreads();
    __threadfence();
    if (threadIdx.x == 0) {
        atomicAdd(&g_bar, 1u);
        while (*(volatile unsigned int*)&g_bar < goal) __nanosleep(32);
        __threadfence();
    }
    __syncthreads();
}

__global__ void __launch_bounds__(128) pinv_fused()
{
    __shared__ float As[64][36];
    __shared__ float Bs[32][68];
    __shared__ float cred[8][16];
    __shared__ float s_inv;
    const int cta = blockIdx.x;
    const int b = cta >> 4, tile = cta & 15;
    const int m0 = (tile >> 2) * 64, n0 = (tile & 3) * 64;
    const long long base = (long long)b * (MLM*MLM);
    const float* X = g_a2 + base;
    float* Z  = g_z  + base;
    float* Zn = g_z2 + base;
    float* XZ = g_xz + base;
    float* T2 = g_t2 + base;
    float* T4 = g_t4 + base;
    const int tid = threadIdx.x;

    // ---- stage A: abs row/col sums + global maxes -------------------------
    {
        int rsub = tid & 7;
        int row  = (tile << 4) + (tid >> 3);
        const float* rp = X + (size_t)row*MLM + rsub*32;
        float s = 0.f;
#pragma unroll
        for (int jj = 0; jj < 8; jj++) {
            float4 f = *(const float4*)(rp + jj*4);
            s += fabsf(f.x) + fabsf(f.y) + fabsf(f.z) + fabsf(f.w);
        }
        s += __shfl_down_sync(~0u, s, 4);
        s += __shfl_down_sync(~0u, s, 2);
        s += __shfl_down_sync(~0u, s, 1);
        if (rsub == 0) atomicMax(&g_cmax, __float_as_uint(s));

        int col = (tile << 4) + (tid & 15);
        int rc  = tid >> 4;
        float cs = 0.f;
        for (int i = 0; i < 32; i++)
            cs += fabsf(X[(size_t)(rc + i*8)*MLM + col]);
        cred[rc][tid & 15] = cs;
        __syncthreads();
        if (tid < 16) {
            float v = 0.f;
#pragma unroll
            for (int i = 0; i < 8; i++) v += cred[i][tid];
            atomicMax(&g_rmax, __float_as_uint(v));
        }
    }
    grid_bar(PINV_CTAS * 1);

    // ---- stage B: z = X^T / (cmax*rmax) ------------------------------------
    if (tid == 0) {
        float cm = __uint_as_float(atomicAdd(&g_cmax, 0u));
        float rm = __uint_as_float(atomicAdd(&g_rmax, 0u));
        s_inv = 1.f / (cm * rm);
    }
    __syncthreads();
    {
        float inv = s_inv;
        for (int idx = tid; idx < 64*64; idx += 128) {
            int r = idx >> 6, c = idx & 63;
            Z[(size_t)(m0+r)*MLM + n0 + c] = X[(size_t)(n0+c)*MLM + m0 + r] * inv;
        }
    }
    grid_bar(PINV_CTAS * 2);

    // ---- iterations ---------------------------------------------------------
    unsigned int step = 2;
    for (int it = 0; it < PITERS; it++) {
        tf32_tile(X,  Z,  nullptr, XZ, 1.f,    0.f,   m0, n0, As, Bs); grid_bar(PINV_CTAS*(++step));
        tf32_tile(XZ, XZ, XZ,      T2, -1.f,   7.f,   m0, n0, As, Bs); grid_bar(PINV_CTAS*(++step));
        tf32_tile(XZ, T2, XZ,      T4, -1.f,   15.f,  m0, n0, As, Bs); grid_bar(PINV_CTAS*(++step));
        tf32_tile(Z,  T4, Z,       Zn, -0.25f, 3.25f, m0, n0, As, Bs);
        float* tmp = Z; Z = Zn; Zn = tmp;
        if (it + 1 < PITERS) grid_bar(PINV_CTAS*(++step));
    }
}

__global__ void zero_bar_kernel()
{
    if (threadIdx.x == 0) { g_bar = 0u; g_cmax = 0u; g_rmax = 0u; }
}

// ---------------- converters ---------------------------------------------------
__global__ void f2bf_kernel(const float* __restrict__ in, __nv_bfloat16* __restrict__ out, int n4)
{
    int i = blockIdx.x * 256 + threadIdx.x;
    if (i < n4) {
        float4 f = ((const float4*)in)[i];
        ((__nv_bfloat162*)out)[2*i]   = __floats2bfloat162_rn(f.x, f.y);
        ((__nv_bfloat162*)out)[2*i+1] = __floats2bfloat162_rn(f.z, f.w);
    }
}

__global__ void tconv_kernel(const float* __restrict__ in, __nv_bfloat16* __restrict__ out,
                             int R, int C, long long bsI, long long bsO)
{
    __shared__ float t[32][33];
    const float* ib = in + (long long)blockIdx.z * bsI;
    __nv_bfloat16* ob = out + (long long)blockIdx.z * bsO;
    int r0 = blockIdx.y * 32, c0 = blockIdx.x * 32;
    int tx = threadIdx.x, ty = threadIdx.y;
#pragma unroll
    for (int i = 0; i < 4; i++)
        t[ty + 8*i][tx] = ib[(size_t)(r0 + ty + 8*i) * C + c0 + tx];
    __syncthreads();
#pragma unroll
    for (int i = 0; i < 4; i++)
        ob[(size_t)(c0 + ty + 8*i) * R + r0 + tx] = __float2bfloat16(t[tx][ty + 8*i]);
}

// ---------------- fp32 SGEMM (B fp32) and bf16-A split-K variant ----------------
template<int BM,int BN,int BK,int TM,int TN, bool ABF>
__global__ void sgemm_k(const void* __restrict__ Av, const float* __restrict__ B,
                        const float* __restrict__ D, const float* __restrict__ bias,
                        float* __restrict__ C,
                        int Md,int Nd,int Kd,
                        int lda,int ldb,int ldc,
                        long long bsA,long long bsB,long long bsD,long long bsC,
                        float alpha,float beta,
                        int transB,int ksplit)
{
    constexpr int THREADS = (BM/TM)*(BN/TN);
    __shared__ float As[BK][BM];
    __shared__ float Bs[BK][BN];
    const int tid = threadIdx.x;
    const int bz  = blockIdx.z;
    const int my  = blockIdx.y / ksplit;
    const int ks  = blockIdx.y % ksplit;
    const int m0  = my * BM;
    const int n0  = blockIdx.x * BN;
    const int kchunk = Kd / ksplit;
    const int k0beg  = ks * kchunk;
    const int k0end  = k0beg + kchunk;

    const float* Bb = B + (long long)bz * bsB;

    float acc[TM][TN];
#pragma unroll
    for (int i = 0; i < TM; i++)
#pragma unroll
        for (int j = 0; j < TN; j++) acc[i][j] = 0.f;

    const int rowBase = (tid / (BN/TN)) * TM;
    const int colBase = (tid % (BN/TN)) * TN;

    for (int k0 = k0beg; k0 < k0end; k0 += BK) {
        if (!ABF) {
            const float* Ab = (const float*)Av + (long long)bz * bsA;
            constexpr int V = BM*BK/4/THREADS;
#pragma unroll
            for (int t = 0; t < V; t++) {
                int idx = tid + t*THREADS;
                int r   = idx / (BK/4);
                int cq  = (idx % (BK/4)) * 4;
                float4 f = *(const float4*)&Ab[(size_t)(m0+r)*lda + k0 + cq];
                As[cq+0][r]=f.x; As[cq+1][r]=f.y; As[cq+2][r]=f.z; As[cq+3][r]=f.w;
            }
        } else {
            const __nv_bfloat16* Ab = (const __nv_bfloat16*)Av + (long long)bz * bsA;
            constexpr int V = BM*BK/4/THREADS;
#pragma unroll
            for (int t = 0; t < V; t++) {
                int idx = tid + t*THREADS;
                int r   = idx / (BK/4);
                int cq  = (idx % (BK/4)) * 4;
                __nv_bfloat162 p0 = *(const __nv_bfloat162*)&Ab[(size_t)(m0+r)*lda + k0 + cq];
                __nv_bfloat162 p1 = *(const __nv_bfloat162*)&Ab[(size_t)(m0+r)*lda + k0 + cq + 2];
                As[cq+0][r]=__bfloat162float(p0.x); As[cq+1][r]=__bfloat162float(p0.y);
                As[cq+2][r]=__bfloat162float(p1.x); As[cq+3][r]=__bfloat162float(p1.y);
            }
        }
        if (!transB) {
            constexpr int V = BK*BN/4/THREADS;
#pragma unroll
            for (int t = 0; t < V; t++) {
                int idx = tid + t*THREADS;
                int c   = idx / (BN/4);
                int jq  = (idx % (BN/4)) * 4;
                *(float4*)&Bs[c][jq] = *(const float4*)&Bb[(size_t)(k0+c)*ldb + n0 + jq];
            }
        } else {
            constexpr int V = BK*BN/4/THREADS;
#pragma unroll
            for (int t = 0; t < V; t++) {
                int idx = tid + t*THREADS;
                int j   = idx / (BK/4);
                int cq  = (idx % (BK/4)) * 4;
                float4 f = *(const float4*)&Bb[(size_t)(n0+j)*ldb + k0 + cq];
                Bs[cq+0][j]=f.x; Bs[cq+1][j]=f.y; Bs[cq+2][j]=f.z; Bs[cq+3][j]=f.w;
            }
        }
        __syncthreads();
#pragma unroll
        for (int kk = 0; kk < BK; kk++) {
            float a[TM], b[TN];
#pragma unroll
            for (int i = 0; i < TM; i++) a[i] = As[kk][rowBase+i];
#pragma unroll
            for (int j = 0; j < TN; j++) b[j] = Bs[kk][colBase+j];
#pragma unroll
            for (int i = 0; i < TM; i++)
#pragma unroll
                for (int j = 0; j < TN; j++) acc[i][j] = fmaf(a[i], b[j], acc[i][j]);
        }
        __syncthreads();
    }

    float* Cb = C + (long long)bz * bsC;
    if (ksplit > 1) {
#pragma unroll
        for (int i = 0; i < TM; i++) {
            size_t off = (size_t)(m0+rowBase+i)*ldc + n0 + colBase;
#pragma unroll
            for (int j = 0; j < TN; j++) atomicAdd(&Cb[off+j], alpha*acc[i][j]);
        }
    } else {
        const float* Db = D ? D + (long long)bz * bsD : nullptr;
#pragma unroll
        for (int i = 0; i < TM; i++) {
            size_t off = (size_t)(m0+rowBase+i)*ldc + n0 + colBase;
#pragma unroll
            for (int j = 0; j < TN; j++) {
                float cv = alpha*acc[i][j];
                if (Db)   cv += beta * Db[off+j];
                if (bias) cv += bias[n0+colBase+j];
                Cb[off+j] = cv;
            }
        }
    }
}

// ---------------- LayerNorm (bf16 out) ------------------------------------------
__global__ void ln_kernel(const float* __restrict__ x, const float* __restrict__ g,
                          const float* __restrict__ b, __nv_bfloat16* __restrict__ xn)
{
    const int t = blockIdx.x;
    const float* xr = x + (size_t)t * DIMF;
    float v0 = xr[threadIdx.x], v1 = xr[threadIdx.x + 256];
    float s = v0 + v1, ss = v0*v0 + v1*v1;
    __shared__ float red0[8], red1[8];
    for (int o = 16; o; o >>= 1) { s += __shfl_down_sync(~0u, s, o); ss += __shfl_down_sync(~0u, ss, o); }
    int w = threadIdx.x >> 5, l = threadIdx.x & 31;
    if (l == 0) { red0[w] = s; red1[w] = ss; }
    __syncthreads();
    __shared__ float mu_s, rs_s;
    if (threadIdx.x == 0) {
        float S = 0, SS = 0;
        for (int i = 0; i < 8; i++) { S += red0[i]; SS += red1[i]; }
        float mu  = S / DIMF;
        float var = SS / DIMF - mu*mu;
        mu_s = mu; rs_s = rsqrtf(var + EPSLN);
    }
    __syncthreads();
    float mu = mu_s, rs = rs_s;
    __nv_bfloat16* o = xn + (size_t)t * DIMF;
    o[threadIdx.x]       = __float2bfloat16((v0 - mu)*rs*g[threadIdx.x]       + b[threadIdx.x]);
    o[threadIdx.x + 256] = __float2bfloat16((v1 - mu)*rs*g[threadIdx.x + 256] + b[threadIdx.x + 256]);
}

// ---------------- landmark means: fp32 + scaled bf16 in one pass ------------------
__global__ void landmark_kernel(const float* __restrict__ qkv,
                                float* __restrict__ ql, float* __restrict__ kl,
                                __nv_bfloat16* __restrict__ qlb, __nv_bfloat16* __restrict__ klb)
{
    int bm = blockIdx.x * 4 + (threadIdx.x >> 6);
    int b = bm / MLM, m = bm % MLM;
    int d = threadIdx.x & 63;
    const float* qb = qkv + ((size_t)b*SEQ + (size_t)m*LRED)*QKVW + d;
    const float* kb = qb + 64;
    float sq = 0, sk = 0;
#pragma unroll
    for (int i = 0; i < LRED; i++) { sq += qb[i*QKVW]; sk += kb[i*QKVW]; }
    sq /= (float)LRED; sk /= (float)LRED;
    ql[(size_t)bm*DH + d] = sq;
    kl[(size_t)bm*DH + d] = sk;
    qlb[(size_t)bm*DH + d] = __float2bfloat16(sq * QSCALE);
    klb[(size_t)bm*DH + d] = __float2bfloat16(sk * QSCALE);
}

// ---------------- softmaxes ---------------------------------------------------------
__global__ void softmax_kernel(float* __restrict__ p, int cols)
{
    extern __shared__ float buf[];
    __shared__ float red[32];
    float* x = p + (size_t)blockIdx.x * cols;
    int tid = threadIdx.x;
    float m = -1e30f;
    for (int c = tid; c < cols; c += blockDim.x) { float v = x[c]; buf[c] = v; m = fmaxf(m, v); }
    for (int o = 16; o; o >>= 1) m = fmaxf(m, __shfl_xor_sync(~0u, m, o));
    if ((tid & 31) == 0) red[tid >> 5] = m;
    __syncthreads();
    if (tid == 0) { float v = -1e30f; for (int i = 0; i < (int)blockDim.x/32; i++) v = fmaxf(v, red[i]); red[0] = v; }
    __syncthreads();
    m = red[0];
    float s = 0;
    for (int c = tid; c < cols; c += blockDim.x) { float e = expf(buf[c] - m); buf[c] = e; s += e; }
    __syncthreads();
    for (int o = 16; o; o >>= 1) s += __shfl_xor_sync(~0u, s, o);
    if ((tid & 31) == 0) red[tid >> 5] = s;
    __syncthreads();
    if (tid == 0) { float v = 0; for (int i = 0; i < (int)blockDim.x/32; i++) v += red[i]; red[0] = v; }
    __syncthreads();
    float inv = 1.f / red[0];
    for (int c = tid; c < cols; c += blockDim.x) x[c] = buf[c] * inv;
}

// bf16 in-place softmax
__global__ void softmax_b16io_kernel(__nv_bfloat16* __restrict__ p, int cols)
{
    extern __shared__ float buf[];
    __shared__ float red[32];
    __nv_bfloat16* x = p + (size_t)blockIdx.x * cols;
    int tid = threadIdx.x;
    float m = -1e30f;
    for (int c = tid; c < cols; c += blockDim.x) {
        float v = __bfloat162float(x[c]); buf[c] = v; m = fmaxf(m, v);
    }
    for (int o = 16; o; o >>= 1) m = fmaxf(m, __shfl_xor_sync(~0u, m, o));
    if ((tid & 31) == 0) red[tid >> 5] = m;
    __syncthreads();
    if (tid == 0) { float v = -1e30f; for (int i = 0; i < (int)blockDim.x/32; i++) v = fmaxf(v, red[i]); red[0] = v; }
    __syncthreads();
    m = red[0];
    float s = 0;
    for (int c = tid; c < cols; c += blockDim.x) { float e = expf(buf[c] - m); buf[c] = e; s += e; }
    __syncthreads();
    for (int o = 16; o; o >>= 1) s += __shfl_xor_sync(~0u, s, o);
    if ((tid & 31) == 0) red[tid >> 5] = s;
    __syncthreads();
    if (tid == 0) { float v = 0; for (int i = 0; i < (int)blockDim.x/32; i++) v += red[i]; red[0] = v; }
    __syncthreads();
    float inv = 1.f / red[0];
    for (int c = tid; c < cols; c += blockDim.x) x[c] = __float2bfloat16(buf[c] * inv);
}

// ---------------- depthwise conv: cv = conv(v) (fp32) ------------------------------
#define CTOK 64
__global__ void conv_kernel(const float* __restrict__ qkv, const float* __restrict__ wc,
                            float* __restrict__ cv)
{
    __shared__ float sv[CTOK + KSZ - 1][DH];
    __shared__ float swc[KSZ];
    const int b  = blockIdx.y;
    const int n0 = blockIdx.x * CTOK;
    const int tid = threadIdx.x;
    if (tid < KSZ) swc[tid] = wc[tid];
    const float* vb = qkv + (size_t)b * SEQ * QKVW + 128;
    const int half = KSZ / 2;
    for (int idx = tid; idx < (CTOK + KSZ - 1) * DH; idx += 256) {
        int r = idx / DH, d = idx % DH;
        int n = n0 - half + r;
        sv[r][d] = (n >= 0 && n < SEQ) ? vb[(size_t)n*QKVW + d] : 0.f;
    }
    __syncthreads();
    int d = tid % DH, tr = tid / DH;
    for (int t = tr; t < CTOK; t += 4) {
        float acc = 0;
#pragma unroll
        for (int j = 0; j < KSZ; j++) acc += sv[t + j][d] * swc[j];
        cv[((size_t)b*SEQ + n0 + t)*DH + d] = acc;
    }
}

__global__ void zero_kernel(float* p, int n)
{
    int i = blockIdx.x * 256 + threadIdx.x;
    if (i < n) p[i] = 0.f;
}

// ---------------- launcher --------------------------------------------------------
extern "C" void kernel_launch(void* const* d_in, const int* in_sizes, int n_in,
                              void* d_out, int out_size)
{
    static cudaStream_t s1 = nullptr, s2 = nullptr;
    static cudaEvent_t eL = nullptr, e1 = nullptr, e2 = nullptr, eLft = nullptr, e3 = nullptr;
    if (!s1) {
        cudaStreamCreateWithFlags(&s1, cudaStreamNonBlocking);
        cudaStreamCreateWithFlags(&s2, cudaStreamNonBlocking);
        cudaEventCreateWithFlags(&eL, cudaEventDisableTiming);
        cudaEventCreateWithFlags(&e1, cudaEventDisableTiming);
        cudaEventCreateWithFlags(&e2, cudaEventDisableTiming);
        cudaEventCreateWithFlags(&eLft, cudaEventDisableTiming);
        cudaEventCreateWithFlags(&e3, cudaEventDisableTiming);
        cudaFuncSetAttribute(hgemm_wide<0,true>,
            cudaFuncAttributeMaxDynamicSharedMemorySize, 98304);
    }

    const float* x      = (const float*)d_in[0];
    const float* gamma  = (const float*)d_in[1];
    const float* betap  = (const float*)d_in[2];
    const float* w_qkv  = (const float*)d_in[3];
    const float* w_out  = (const float*)d_in[4];
    const float* b_out  = (const float*)d_in[5];
    const float* w_conv = (const float*)d_in[6];

    float* y    = (float*)d_out;
    float* attn = (float*)d_out + (size_t)TOK * DIMF;

    float *qkv,*ql,*kl,*a2,*z,*a3v,*cv;
    __nv_bfloat16 *xnb,*wqkvTb,*woutTb,*qkvb,*qlb,*klb,*a1b,*zb,*leftb,*a3b,*a3vTb,*ohb;
    cudaGetSymbolAddress((void**)&qkv,  g_qkv);
    cudaGetSymbolAddress((void**)&ql,   g_ql);
    cudaGetSymbolAddress((void**)&kl,   g_kl);
    cudaGetSymbolAddress((void**)&a2,   g_a2);
    cudaGetSymbolAddress((void**)&z,    g_z);
    cudaGetSymbolAddress((void**)&a3v,  g_a3v);
    cudaGetSymbolAddress((void**)&cv,   g_cv);
    cudaGetSymbolAddress((void**)&xnb,  g_xnb);
    cudaGetSymbolAddress((void**)&wqkvTb, g_wqkvTb);
    cudaGetSymbolAddress((void**)&woutTb, g_woutTb);
    cudaGetSymbolAddress((void**)&qkvb, g_qkvb);
    cudaGetSymbolAddress((void**)&qlb,  g_qlb);
    cudaGetSymbolAddress((void**)&klb,  g_klb);
    cudaGetSymbolAddress((void**)&a1b,  g_a1b);
    cudaGetSymbolAddress((void**)&zb,   g_zb);
    cudaGetSymbolAddress((void**)&leftb,g_leftb);
    cudaGetSymbolAddress((void**)&a3b,  g_a3b);
    cudaGetSymbolAddress((void**)&a3vTb,g_a3vTb);
    cudaGetSymbolAddress((void**)&ohb,  g_ohb);

    const long long bsM = (long long)MLM*MLM;
    const float* v = qkv + 128;
    const __nv_bfloat16* qkb_q = qkvb;
    const __nv_bfloat16* qkb_k = qkvb + 64;

    // -------- main stream: spine --------
    ln_kernel<<<TOK, 256>>>(x, gamma, betap, xnb);
    tconv_kernel<<<dim3(QKVW/32, DIMF/32, 1), dim3(32,8)>>>(w_qkv, wqkvTb, DIMF, QKVW, 0, 0);
    tconv_kernel<<<dim3(DIMF/32, DH/32, 1), dim3(32,8)>>>(w_out, woutTb, DH, DIMF, 0, 0);
    {
        dim3 g(QKVW/64, TOK/128, 1);
        hgemm_tt<64,1,false><<<g, 256>>>(xnb, wqkvTb, qkv, qkvb, nullptr, nullptr,
            DIMF, DIMF, DIMF, QKVW, 0, 0, 0);
    }
    landmark_kernel<<<BATCH*MLM/4, 256>>>(qkv, ql, kl, qlb, klb);
    cudaEventRecord(eL, 0);

    // -------- branch 1: sim1 -> softmax(a1b) --------
    cudaStreamWaitEvent(s1, eL, 0);
    {
        dim3 g(MLM/128, SEQ/128, BATCH);
        hgemm_tt<128,2,false><<<g, 256, 0, s1>>>(qkb_q, klb, nullptr, a1b, nullptr, nullptr,
            DH, QKVW, DH, MLM, (long long)SEQ*QKVW, (long long)MLM*DH, (long long)SEQ*MLM);
    }
    softmax_b16io_kernel<<<BATCH*SEQ, 256, MLM*4, s1>>>(a1b, MLM);
    cudaEventRecord(e1, s1);

    // -------- branch 2: sim3 -> softmax(a3b) -> a3v -> a3vT ; conv --------
    cudaStreamWaitEvent(s2, eL, 0);
    {
        dim3 g(SEQ/128, MLM/128, BATCH);
        hgemm_tt<128,2,false><<<g, 256, 0, s2>>>(qlb, qkb_k, nullptr, a3b, nullptr, nullptr,
            DH, DH, QKVW, SEQ, (long long)MLM*DH, (long long)SEQ*QKVW, (long long)MLM*SEQ);
    }
    softmax_b16io_kernel<<<BATCH*MLM, 256, SEQ*4, s2>>>(a3b, SEQ);
    zero_kernel<<<(BATCH*MLM*DH + 255)/256, 256, 0, s2>>>(a3v, BATCH*MLM*DH);
    {
        dim3 g(DH/64, (MLM/64)*32, BATCH);
        sgemm_k<64,64,16,4,4,true><<<g, 256, 0, s2>>>(a3b, v, nullptr, nullptr, a3v,
            MLM, DH, SEQ, SEQ, QKVW, DH,
            (long long)MLM*SEQ, (long long)SEQ*QKVW, 0, (long long)MLM*DH, 1.f, 0.f, 0, 32);
    }
    tconv_kernel<<<dim3(DH/32, MLM/32, BATCH), dim3(32,8), 0, s2>>>(a3v, a3vTb, MLM, DH,
        (long long)MLM*DH, (long long)MLM*DH);
    conv_kernel<<<dim3(SEQ/CTOK, BATCH), 256, 0, s2>>>(qkv, w_conv, cv);
    cudaEventRecord(e2, s2);

    // -------- spine continues: sim2 -> softmax -> pinv --------
    {
        dim3 g(MLM/32, MLM/32, BATCH);
        sgemm_k<32,32,32,2,2,false><<<g, 256>>>(ql, kl, nullptr, nullptr, a2,
            MLM, MLM, DH, DH, DH, MLM,
            (long long)MLM*DH, (long long)MLM*DH, 0, bsM, QSCALE, 0.f, 1, 1);
    }
    softmax_kernel<<<BATCH*MLM, 256, MLM*4>>>(a2, MLM);
    zero_bar_kernel<<<1, 32>>>();
    pinv_fused<<<PINV_CTAS, 128>>>();     // result in g_z
    f2bf_kernel<<<(BATCH*MLM*MLM/4 + 255)/256, 256>>>(z, zb, BATCH*MLM*MLM/4);

    // -------- join: left needs a1b --------
    cudaStreamWaitEvent(0, e1, 0);
    {
        dim3 g(MLM/128, SEQ/128, BATCH);
        hgemm_tt<128,2,true><<<g, 256>>>(a1b, zb, nullptr, leftb, nullptr, nullptr,
            MLM, MLM, MLM, MLM, (long long)SEQ*MLM, bsM, (long long)SEQ*MLM);
    }
    cudaEventRecord(eLft, 0);

    // -------- side stream: oh + projection (overlaps attn) --------
    cudaStreamWaitEvent(s1, eLft, 0);
    cudaStreamWaitEvent(s1, e2, 0);
    {
        dim3 g(1, SEQ/128, BATCH);
        hgemm_tt<64,4,false><<<g, 256, 0, s1>>>(leftb, a3vTb, nullptr, ohb, cv, nullptr,
            MLM, MLM, MLM, DH, (long long)SEQ*MLM, (long long)DH*MLM, (long long)SEQ*DH);
    }
    {
        dim3 g(DIMF/128, TOK/128, 1);
        hgemm_tt<128,3,false><<<g, 256, 0, s1>>>(ohb, woutTb, y, nullptr, x, b_out,
            DH, DH, DH, DIMF, 0, 0, 0);
    }
    cudaEventRecord(e3, s1);

    // -------- main stream: attn = leftb @ a3b (wide 128x256 tile) --------
    {
        dim3 g(SEQ/256, SEQ/128, BATCH);
        hgemm_wide<0,true><<<g, 256, 98304>>>(leftb, a3b, attn, nullptr,
            MLM, MLM, SEQ, SEQ, (long long)SEQ*MLM, (long long)MLM*SEQ, (long long)SEQ*SEQ);
    }
    cudaStreamWaitEvent(0, e3, 0);
}

// round 12
// speedup vs baseline: 1.0418x; 1.0418x over previous
#include <cuda_runtime.h>
#include <cuda_bf16.h>
#include <math.h>
#include <cstdint>

#define DIMF 512
#define DH 64
#define MLM 256
#define BATCH 4
#define SEQ 4096
#define TOK (BATCH*SEQ)
#define LRED (SEQ/MLM)
#define PITERS 6
#define QSCALE 0.125f
#define KSZ 33
#define EPSLN 1e-5f
#define QKVW 192
#define PINV_CTAS 64

// ---------------- scratch (device globals; no runtime allocation) ------------
__device__ float g_qkv[TOK*QKVW];
__device__ float g_ql[BATCH*MLM*DH];
__device__ float g_kl[BATCH*MLM*DH];
__device__ float g_a2[BATCH*MLM*MLM];
__device__ float g_z[BATCH*MLM*MLM];
__device__ float g_z2[BATCH*MLM*MLM];
__device__ float g_xz[BATCH*MLM*MLM];
__device__ float g_t2[BATCH*MLM*MLM];
__device__ float g_t4[BATCH*MLM*MLM];
__device__ float g_a3v[BATCH*MLM*DH];
__device__ float g_cv[TOK*DH];
__device__ unsigned int g_cmax;
__device__ unsigned int g_rmax;
__device__ unsigned int g_bar;
// bf16 operands
__device__ __nv_bfloat16 g_xnb[TOK*DIMF];
__device__ __nv_bfloat16 g_wqkvTb[QKVW*DIMF];
__device__ __nv_bfloat16 g_woutTb[DIMF*DH];
__device__ __nv_bfloat16 g_qkvb[TOK*QKVW];
__device__ __nv_bfloat16 g_qlb[BATCH*MLM*DH];
__device__ __nv_bfloat16 g_klb[BATCH*MLM*DH];
__device__ __nv_bfloat16 g_a1b[(size_t)BATCH*SEQ*MLM];
__device__ __nv_bfloat16 g_zb[BATCH*MLM*MLM];
__device__ __nv_bfloat16 g_leftb[(size_t)BATCH*SEQ*MLM];
__device__ __nv_bfloat16 g_a3b[(size_t)BATCH*MLM*SEQ];
__device__ __nv_bfloat16 g_a3vTb[BATCH*DH*MLM];
__device__ __nv_bfloat16 g_ohb[TOK*DH];

__device__ __forceinline__ uint32_t smem_u32(const void* p) {
    uint32_t a;
    asm("{ .reg .u64 t; cvta.to.shared.u64 t, %1; cvt.u32.u64 %0, t; }" : "=r"(a) : "l"(p));
    return a;
}
__device__ __forceinline__ void cp_async16(uint32_t dst, const void* src) {
    asm volatile("cp.async.cg.shared.global [%0], [%1], 16;" :: "r"(dst), "l"(src));
}
__device__ __forceinline__ float tf32r(float v) {
    uint32_t u;
    asm("cvt.rna.tf32.f32 %0, %1;" : "=r"(u) : "f"(v));
    return __uint_as_float(u);
}

// =============== pipelined bf16 HMMA GEMM (128 x BN x 64) =====================
// C[M,N] = A[M,K] @ B^T.  TB=false: B [N,K]; TB=true: B [K,N] via ldmatrix.trans.
// OM: 0 = fp32 out, 1 = fp32 + bf16 mirror, 2 = bf16 only,
//     3 = fp32 out: C = acc + D + bias,  4 = bf16 only: C2 = bf16(acc + D).
template<int BN, int OM, bool TB>
__global__ void __launch_bounds__(256) hgemm_tt(
    const __nv_bfloat16* __restrict__ A, const __nv_bfloat16* __restrict__ B,
    float* __restrict__ C, __nv_bfloat16* __restrict__ C2,
    const float* __restrict__ Dp, const float* __restrict__ biasp,
    int K, int lda, int ldb, int ldc,
    long long bsA, long long bsB, long long bsC)
{
    constexpr int NJ = BN / 32;
    __shared__ __align__(16) char sA[2][128*128];
    __shared__ __align__(16) char sB[2][BN*128];
    const int tid = threadIdx.x, lane = tid & 31, w = tid >> 5;
    const int wm = (w & 3) * 32, wn = (w >> 2) * (BN/2);
    const int m0 = blockIdx.y * 128, n0 = blockIdx.x * BN, bz = blockIdx.z;
    const __nv_bfloat16* Ag = A + (long long)bz*bsA + (size_t)m0*lda;
    const __nv_bfloat16* Bg = B + (long long)bz*bsB + (TB ? (size_t)n0 : (size_t)n0*ldb);
    const uint32_t sAu = smem_u32(sA), sBu = smem_u32(sB);

    float acc[2][NJ*2][4];
#pragma unroll
    for (int i = 0; i < 2; i++)
#pragma unroll
      for (int j = 0; j < NJ*2; j++)
#pragma unroll
        for (int t = 0; t < 4; t++) acc[i][j][t] = 0.f;

    const int sub = lane >> 3, rr = lane & 7;
    const int lrow = ((sub & 1) << 3) + rr;
    const int lcbb = (sub >> 1) << 4;

    auto loadTiles = [&](int buf, int kt) {
#pragma unroll
        for (int t = 0; t < 4; t++) {
            int idx = tid + t*256, r = idx >> 3, q = idx & 7;
            cp_async16(sAu + buf*16384 + r*128 + ((q*16) ^ ((r & 7) << 4)),
                       Ag + (size_t)r*lda + kt*64 + q*8);
        }
#pragma unroll
        for (int t = 0; t < BN/32; t++) {
            int idx = tid + t*256;
            if (TB) {
                constexpr int CH = BN/8;
                int r = idx / CH, q = idx % CH;
                cp_async16(sBu + buf*(BN*128) + r*(BN*2) + ((q*16) ^ ((r & 7) << 4)),
                           Bg + (size_t)(kt*64 + r)*ldb + q*8);
            } else {
                int r = idx >> 3, q = idx & 7;
                cp_async16(sBu + buf*(BN*128) + r*128 + ((q*16) ^ ((r & 7) << 4)),
                           Bg + (size_t)r*ldb + kt*64 + q*8);
            }
        }
        asm volatile("cp.async.commit_group;");
    };

    const int nt = K >> 6;
    loadTiles(0, 0);
    for (int kt = 0; kt < nt; kt++) {
        if (kt + 1 < nt) {
            loadTiles((kt+1) & 1, kt+1);
            asm volatile("cp.async.wait_group 1;");
        } else {
            asm volatile("cp.async.wait_group 0;");
        }
        __syncthreads();
        const uint32_t aB = sAu + (kt & 1)*16384;
        const uint32_t bB = sBu + (kt & 1)*(BN*128);
#pragma unroll
        for (int ks = 0; ks < 4; ks++) {
            uint32_t a[2][4], b[NJ][4];
            const int lcb = ks*32 + lcbb;
#pragma unroll
            for (int mi = 0; mi < 2; mi++) {
                int r = wm + mi*16 + lrow;
                uint32_t ad = aB + r*128 + (lcb ^ ((r & 7) << 4));
                asm volatile("ldmatrix.sync.aligned.m8n8.x4.shared.b16 {%0,%1,%2,%3}, [%4];"
                  : "=r"(a[mi][0]),"=r"(a[mi][1]),"=r"(a[mi][2]),"=r"(a[mi][3]) : "r"(ad));
            }
#pragma unroll
            for (int nj = 0; nj < NJ; nj++) {
                if (TB) {
                    int row = ks*16 + (lane & 15);
                    int bc  = (wn + nj*16 + (lane >> 4)*8) * 2;
                    uint32_t bd = bB + row*(BN*2) + (bc ^ ((row & 7) << 4));
                    asm volatile("ldmatrix.sync.aligned.m8n8.x4.trans.shared.b16 {%0,%1,%2,%3}, [%4];"
                      : "=r"(b[nj][0]),"=r"(b[nj][1]),"=r"(b[nj][2]),"=r"(b[nj][3]) : "r"(bd));
                } else {
                    int r = wn + nj*16 + lrow;
                    uint32_t bd = bB + r*128 + (lcb ^ ((r & 7) << 4));
                    asm volatile("ldmatrix.sync.aligned.m8n8.x4.shared.b16 {%0,%1,%2,%3}, [%4];"
                      : "=r"(b[nj][0]),"=r"(b[nj][1]),"=r"(b[nj][2]),"=r"(b[nj][3]) : "r"(bd));
                }
            }
#pragma unroll
            for (int mi = 0; mi < 2; mi++)
#pragma unroll
              for (int nj = 0; nj < NJ; nj++)
#pragma unroll
                for (int s = 0; s < 2; s++) {
                    float* c = acc[mi][nj*2+s];
                    uint32_t b0 = TB ? b[nj][2*s]   : b[nj][s];
                    uint32_t b1 = TB ? b[nj][2*s+1] : b[nj][s+2];
                    asm volatile("mma.sync.aligned.m16n8k16.row.col.f32.bf16.bf16.f32 "
                        "{%0,%1,%2,%3}, {%4,%5,%6,%7}, {%8,%9}, {%0,%1,%2,%3};"
                        : "+f"(c[0]),"+f"(c[1]),"+f"(c[2]),"+f"(c[3])
                        : "r"(a[mi][0]),"r"(a[mi][1]),"r"(a[mi][2]),"r"(a[mi][3]),
                          "r"(b0),"r"(b1));
                }
        }
        __syncthreads();
    }
    float* Cg = (OM == 0 || OM == 1 || OM == 3) ? C + (long long)bz*bsC + (size_t)m0*ldc + n0 : nullptr;
    __nv_bfloat16* Cg2 = (OM == 1 || OM == 2 || OM == 4) ? C2 + (long long)bz*bsC + (size_t)m0*ldc + n0 : nullptr;
    const float* Dg = (OM == 3 || OM == 4) ? Dp + (long long)bz*bsC + (size_t)m0*ldc + n0 : nullptr;
    const int lr = lane >> 2, lc = lane & 3;
#pragma unroll
    for (int mi = 0; mi < 2; mi++)
#pragma unroll
      for (int ns = 0; ns < NJ*2; ns++) {
          size_t off = (size_t)(wm + mi*16 + lr)*ldc + wn + ns*8 + lc*2;
          float v0 = acc[mi][ns][0], v1 = acc[mi][ns][1];
          float v2 = acc[mi][ns][2], v3 = acc[mi][ns][3];
          if (OM == 3 || OM == 4) {
              float2 d0 = *(const float2*)(Dg + off);
              float2 d1 = *(const float2*)(Dg + off + 8*ldc);
              v0 += d0.x; v1 += d0.y; v2 += d1.x; v3 += d1.y;
              if (OM == 3) {
                  int col = n0 + wn + ns*8 + lc*2;
                  float b0 = biasp[col], b1 = biasp[col+1];
                  v0 += b0; v1 += b1; v2 += b0; v3 += b1;
              }
          }
          if (OM == 0 || OM == 1 || OM == 3) {
              float* p = Cg + off;
              *(float2*)p = make_float2(v0, v1);
              *(float2*)(p + 8*ldc) = make_float2(v2, v3);
          }
          if (OM == 1 || OM == 2 || OM == 4) {
              *(__nv_bfloat162*)(Cg2 + off) = __floats2bfloat162_rn(v0, v1);
              *(__nv_bfloat162*)(Cg2 + off + 8*ldc) = __floats2bfloat162_rn(v2, v3);
          }
      }
}

// =============== fused persistent pinv (init + tf32 tiles + grid barrier) =====
__device__ __forceinline__ void tf32_tile(
    const float* __restrict__ Ab, const float* __restrict__ Bb,
    const float* __restrict__ Db, float* __restrict__ Cb,
    float alpha, float beta, int m0, int n0,
    float (*As)[36], float (*Bs)[68])
{
    const int tid = threadIdx.x, lane = tid & 31, w = tid >> 5;
    const int wm = (w & 1) * 32, wn = (w >> 1) * 32;
    const int g = lane >> 2, t = lane & 3;

    float acc[2][4][4] = {};
    for (int k0 = 0; k0 < MLM; k0 += 32) {
#pragma unroll
        for (int i = 0; i < 4; i++) {
            int idx = tid + i*128;
            {
                int r = idx >> 3, c4 = (idx & 7) * 4;
                float4 f = *(const float4*)&Ab[(size_t)(m0+r)*MLM + k0 + c4];
                As[r][c4+0] = tf32r(f.x); As[r][c4+1] = tf32r(f.y);
                As[r][c4+2] = tf32r(f.z); As[r][c4+3] = tf32r(f.w);
            }
            {
                int r = idx >> 4, c4 = (idx & 15) * 4;
                float4 f = *(const float4*)&Bb[(size_t)(k0+r)*MLM + n0 + c4];
                Bs[r][c4+0] = tf32r(f.x); Bs[r][c4+1] = tf32r(f.y);
                Bs[r][c4+2] = tf32r(f.z); Bs[r][c4+3] = tf32r(f.w);
            }
        }
        __syncthreads();
#pragma unroll
        for (int kk = 0; kk < 32; kk += 8) {
            uint32_t a[2][4], b[4][2];
#pragma unroll
            for (int mi = 0; mi < 2; mi++) {
                int r = wm + mi*16 + g;
                a[mi][0] = __float_as_uint(As[r][kk+t]);
                a[mi][1] = __float_as_uint(As[r+8][kk+t]);
                a[mi][2] = __float_as_uint(As[r][kk+t+4]);
                a[mi][3] = __float_as_uint(As[r+8][kk+t+4]);
            }
#pragma unroll
            for (int nj = 0; nj < 4; nj++) {
                int cN = wn + nj*8 + g;
                b[nj][0] = __float_as_uint(Bs[kk+t][cN]);
                b[nj][1] = __float_as_uint(Bs[kk+t+4][cN]);
            }
#pragma unroll
            for (int mi = 0; mi < 2; mi++)
#pragma unroll
              for (int nj = 0; nj < 4; nj++) {
                  float* c = acc[mi][nj];
                  asm volatile("mma.sync.aligned.m16n8k8.row.col.f32.tf32.tf32.f32 "
                      "{%0,%1,%2,%3}, {%4,%5,%6,%7}, {%8,%9}, {%0,%1,%2,%3};"
                      : "+f"(c[0]),"+f"(c[1]),"+f"(c[2]),"+f"(c[3])
                      : "r"(a[mi][0]),"r"(a[mi][1]),"r"(a[mi][2]),"r"(a[mi][3]),
                        "r"(b[nj][0]),"r"(b[nj][1]));
              }
        }
        __syncthreads();
    }
#pragma unroll
    for (int mi = 0; mi < 2; mi++)
#pragma unroll
      for (int nj = 0; nj < 4; nj++) {
          int r0 = m0 + wm + mi*16 + g;
          int c0 = n0 + wn + nj*8 + t*2;
          float* c = acc[mi][nj];
          float2 v0 = make_float2(alpha*c[0], alpha*c[1]);
          float2 v1 = make_float2(alpha*c[2], alpha*c[3]);
          if (Db) {
              float2 d0 = *(const float2*)&Db[(size_t)r0*MLM + c0];
              float2 d1 = *(const float2*)&Db[(size_t)(r0+8)*MLM + c0];
              v0.x += beta*d0.x; v0.y += beta*d0.y;
              v1.x += beta*d1.x; v1.y += beta*d1.y;
          }
          *(float2*)&Cb[(size_t)r0*MLM + c0] = v0;
          *(float2*)&Cb[(size_t)(r0+8)*MLM + c0] = v1;
      }
}

__device__ __forceinline__ void grid_bar(unsigned int goal)
{
    __syncthreads();
    __threadfence();
    if (threadIdx.x == 0) {
        atomicAdd(&g_bar, 1u);
        while (*(volatile unsigned int*)&g_bar < goal) __nanosleep(32);
        __threadfence();
    }
    __syncthreads();
}

__global__ void __launch_bounds__(128) pinv_fused()
{
    __shared__ float As[64][36];
    __shared__ float Bs[32][68];
    __shared__ float cred[8][16];
    __shared__ float s_inv;
    const int cta = blockIdx.x;
    const int b = cta >> 4, tile = cta & 15;
    const int m0 = (tile >> 2) * 64, n0 = (tile & 3) * 64;
    const long long base = (long long)b * (MLM*MLM);
    const float* X = g_a2 + base;
    float* Z  = g_z  + base;
    float* Zn = g_z2 + base;
    float* XZ = g_xz + base;
    float* T2 = g_t2 + base;
    float* T4 = g_t4 + base;
    const int tid = threadIdx.x;

    {
        int rsub = tid & 7;
        int row  = (tile << 4) + (tid >> 3);
        const float* rp = X + (size_t)row*MLM + rsub*32;
        float s = 0.f;
#pragma unroll
        for (int jj = 0; jj < 8; jj++) {
            float4 f = *(const float4*)(rp + jj*4);
            s += fabsf(f.x) + fabsf(f.y) + fabsf(f.z) + fabsf(f.w);
        }
        s += __shfl_down_sync(~0u, s, 4);
        s += __shfl_down_sync(~0u, s, 2);
        s += __shfl_down_sync(~0u, s, 1);
        if (rsub == 0) atomicMax(&g_cmax, __float_as_uint(s));

        int col = (tile << 4) + (tid & 15);
        int rc  = tid >> 4;
        float cs = 0.f;
        for (int i = 0; i < 32; i++)
            cs += fabsf(X[(size_t)(rc + i*8)*MLM + col]);
        cred[rc][tid & 15] = cs;
        __syncthreads();
        if (tid < 16) {
            float v = 0.f;
#pragma unroll
            for (int i = 0; i < 8; i++) v += cred[i][tid];
            atomicMax(&g_rmax, __float_as_uint(v));
        }
    }
    grid_bar(PINV_CTAS * 1);

    if (tid == 0) {
        float cm = __uint_as_float(atomicAdd(&g_cmax, 0u));
        float rm = __uint_as_float(atomicAdd(&g_rmax, 0u));
        s_inv = 1.f / (cm * rm);
    }
    __syncthreads();
    {
        float inv = s_inv;
        for (int idx = tid; idx < 64*64; idx += 128) {
            int r = idx >> 6, c = idx & 63;
            Z[(size_t)(m0+r)*MLM + n0 + c] = X[(size_t)(n0+c)*MLM + m0 + r] * inv;
        }
    }
    grid_bar(PINV_CTAS * 2);

    unsigned int step = 2;
    for (int it = 0; it < PITERS; it++) {
        tf32_tile(X,  Z,  nullptr, XZ, 1.f,    0.f,   m0, n0, As, Bs); grid_bar(PINV_CTAS*(++step));
        tf32_tile(XZ, XZ, XZ,      T2, -1.f,   7.f,   m0, n0, As, Bs); grid_bar(PINV_CTAS*(++step));
        tf32_tile(XZ, T2, XZ,      T4, -1.f,   15.f,  m0, n0, As, Bs); grid_bar(PINV_CTAS*(++step));
        tf32_tile(Z,  T4, Z,       Zn, -0.25f, 3.25f, m0, n0, As, Bs);
        float* tmp = Z; Z = Zn; Zn = tmp;
        if (it + 1 < PITERS) grid_bar(PINV_CTAS*(++step));
    }
}

__global__ void zero_bar_kernel()
{
    if (threadIdx.x == 0) { g_bar = 0u; g_cmax = 0u; g_rmax = 0u; }
}

// ---------------- converters ---------------------------------------------------
__global__ void f2bf_kernel(const float* __restrict__ in, __nv_bfloat16* __restrict__ out, int n4)
{
    int i = blockIdx.x * 256 + threadIdx.x;
    if (i < n4) {
        float4 f = ((const float4*)in)[i];
        ((__nv_bfloat162*)out)[2*i]   = __floats2bfloat162_rn(f.x, f.y);
        ((__nv_bfloat162*)out)[2*i+1] = __floats2bfloat162_rn(f.z, f.w);
    }
}

__global__ void tconv_kernel(const float* __restrict__ in, __nv_bfloat16* __restrict__ out,
                             int R, int C, long long bsI, long long bsO)
{
    __shared__ float t[32][33];
    const float* ib = in + (long long)blockIdx.z * bsI;
    __nv_bfloat16* ob = out + (long long)blockIdx.z * bsO;
    int r0 = blockIdx.y * 32, c0 = blockIdx.x * 32;
    int tx = threadIdx.x, ty = threadIdx.y;
#pragma unroll
    for (int i = 0; i < 4; i++)
        t[ty + 8*i][tx] = ib[(size_t)(r0 + ty + 8*i) * C + c0 + tx];
    __syncthreads();
#pragma unroll
    for (int i = 0; i < 4; i++)
        ob[(size_t)(c0 + ty + 8*i) * R + r0 + tx] = __float2bfloat16(t[tx][ty + 8*i]);
}

// ---------------- fp32 SGEMM (B fp32) and bf16-A split-K variant ----------------
template<int BM,int BN,int BK,int TM,int TN, bool ABF>
__global__ void sgemm_k(const void* __restrict__ Av, const float* __restrict__ B,
                        const float* __restrict__ D, const float* __restrict__ bias,
                        float* __restrict__ C,
                        int Md,int Nd,int Kd,
                        int lda,int ldb,int ldc,
                        long long bsA,long long bsB,long long bsD,long long bsC,
                        float alpha,float beta,
                        int transB,int ksplit)
{
    constexpr int THREADS = (BM/TM)*(BN/TN);
    __shared__ float As[BK][BM];
    __shared__ float Bs[BK][BN];
    const int tid = threadIdx.x;
    const int bz  = blockIdx.z;
    const int my  = blockIdx.y / ksplit;
    const int ks  = blockIdx.y % ksplit;
    const int m0  = my * BM;
    const int n0  = blockIdx.x * BN;
    const int kchunk = Kd / ksplit;
    const int k0beg  = ks * kchunk;
    const int k0end  = k0beg + kchunk;

    const float* Bb = B + (long long)bz * bsB;

    float acc[TM][TN];
#pragma unroll
    for (int i = 0; i < TM; i++)
#pragma unroll
        for (int j = 0; j < TN; j++) acc[i][j] = 0.f;

    const int rowBase = (tid / (BN/TN)) * TM;
    const int colBase = (tid % (BN/TN)) * TN;

    for (int k0 = k0beg; k0 < k0end; k0 += BK) {
        if (!ABF) {
            const float* Ab = (const float*)Av + (long long)bz * bsA;
            constexpr int V = BM*BK/4/THREADS;
#pragma unroll
            for (int t = 0; t < V; t++) {
                int idx = tid + t*THREADS;
                int r   = idx / (BK/4);
                int cq  = (idx % (BK/4)) * 4;
                float4 f = *(const float4*)&Ab[(size_t)(m0+r)*lda + k0 + cq];
                As[cq+0][r]=f.x; As[cq+1][r]=f.y; As[cq+2][r]=f.z; As[cq+3][r]=f.w;
            }
        } else {
            const __nv_bfloat16* Ab = (const __nv_bfloat16*)Av + (long long)bz * bsA;
            constexpr int V = BM*BK/4/THREADS;
#pragma unroll
            for (int t = 0; t < V; t++) {
                int idx = tid + t*THREADS;
                int r   = idx / (BK/4);
                int cq  = (idx % (BK/4)) * 4;
                __nv_bfloat162 p0 = *(const __nv_bfloat162*)&Ab[(size_t)(m0+r)*lda + k0 + cq];
                __nv_bfloat162 p1 = *(const __nv_bfloat162*)&Ab[(size_t)(m0+r)*lda + k0 + cq + 2];
                As[cq+0][r]=__bfloat162float(p0.x); As[cq+1][r]=__bfloat162float(p0.y);
                As[cq+2][r]=__bfloat162float(p1.x); As[cq+3][r]=__bfloat162float(p1.y);
            }
        }
        if (!transB) {
            constexpr int V = BK*BN/4/THREADS;
#pragma unroll
            for (int t = 0; t < V; t++) {
                int idx = tid + t*THREADS;
                int c   = idx / (BN/4);
                int jq  = (idx % (BN/4)) * 4;
                *(float4*)&Bs[c][jq] = *(const float4*)&Bb[(size_t)(k0+c)*ldb + n0 + jq];
            }
        } else {
            constexpr int V = BK*BN/4/THREADS;
#pragma unroll
            for (int t = 0; t < V; t++) {
                int idx = tid + t*THREADS;
                int j   = idx / (BK/4);
                int cq  = (idx % (BK/4)) * 4;
                float4 f = *(const float4*)&Bb[(size_t)(n0+j)*ldb + k0 + cq];
                Bs[cq+0][j]=f.x; Bs[cq+1][j]=f.y; Bs[cq+2][j]=f.z; Bs[cq+3][j]=f.w;
            }
        }
        __syncthreads();
#pragma unroll
        for (int kk = 0; kk < BK; kk++) {
            float a[TM], b[TN];
#pragma unroll
            for (int i = 0; i < TM; i++) a[i] = As[kk][rowBase+i];
#pragma unroll
            for (int j = 0; j < TN; j++) b[j] = Bs[kk][colBase+j];
#pragma unroll
            for (int i = 0; i < TM; i++)
#pragma unroll
                for (int j = 0; j < TN; j++) acc[i][j] = fmaf(a[i], b[j], acc[i][j]);
        }
        __syncthreads();
    }

    float* Cb = C + (long long)bz * bsC;
    if (ksplit > 1) {
#pragma unroll
        for (int i = 0; i < TM; i++) {
            size_t off = (size_t)(m0+rowBase+i)*ldc + n0 + colBase;
#pragma unroll
            for (int j = 0; j < TN; j++) atomicAdd(&Cb[off+j], alpha*acc[i][j]);
        }
    } else {
        const float* Db = D ? D + (long long)bz * bsD : nullptr;
#pragma unroll
        for (int i = 0; i < TM; i++) {
            size_t off = (size_t)(m0+rowBase+i)*ldc + n0 + colBase;
#pragma unroll
            for (int j = 0; j < TN; j++) {
                float cv = alpha*acc[i][j];
                if (Db)   cv += beta * Db[off+j];
                if (bias) cv += bias[n0+colBase+j];
                Cb[off+j] = cv;
            }
        }
    }
}

// ---------------- LayerNorm (bf16 out) ------------------------------------------
__global__ void ln_kernel(const float* __restrict__ x, const float* __restrict__ g,
                          const float* __restrict__ b, __nv_bfloat16* __restrict__ xn)
{
    const int t = blockIdx.x;
    const float* xr = x + (size_t)t * DIMF;
    float v0 = xr[threadIdx.x], v1 = xr[threadIdx.x + 256];
    float s = v0 + v1, ss = v0*v0 + v1*v1;
    __shared__ float red0[8], red1[8];
    for (int o = 16; o; o >>= 1) { s += __shfl_down_sync(~0u, s, o); ss += __shfl_down_sync(~0u, ss, o); }
    int w = threadIdx.x >> 5, l = threadIdx.x & 31;
    if (l == 0) { red0[w] = s; red1[w] = ss; }
    __syncthreads();
    __shared__ float mu_s, rs_s;
    if (threadIdx.x == 0) {
        float S = 0, SS = 0;
        for (int i = 0; i < 8; i++) { S += red0[i]; SS += red1[i]; }
        float mu  = S / DIMF;
        float var = SS / DIMF - mu*mu;
        mu_s = mu; rs_s = rsqrtf(var + EPSLN);
    }
    __syncthreads();
    float mu = mu_s, rs = rs_s;
    __nv_bfloat16* o = xn + (size_t)t * DIMF;
    o[threadIdx.x]       = __float2bfloat16((v0 - mu)*rs*g[threadIdx.x]       + b[threadIdx.x]);
    o[threadIdx.x + 256] = __float2bfloat16((v1 - mu)*rs*g[threadIdx.x + 256] + b[threadIdx.x + 256]);
}

// ---------------- landmark means: fp32 + scaled bf16 in one pass ------------------
__global__ void landmark_kernel(const float* __restrict__ qkv,
                                float* __restrict__ ql, float* __restrict__ kl,
                                __nv_bfloat16* __restrict__ qlb, __nv_bfloat16* __restrict__ klb)
{
    int bm = blockIdx.x * 4 + (threadIdx.x >> 6);
    int b = bm / MLM, m = bm % MLM;
    int d = threadIdx.x & 63;
    const float* qb = qkv + ((size_t)b*SEQ + (size_t)m*LRED)*QKVW + d;
    const float* kb = qb + 64;
    float sq = 0, sk = 0;
#pragma unroll
    for (int i = 0; i < LRED; i++) { sq += qb[i*QKVW]; sk += kb[i*QKVW]; }
    sq /= (float)LRED; sk /= (float)LRED;
    ql[(size_t)bm*DH + d] = sq;
    kl[(size_t)bm*DH + d] = sk;
    qlb[(size_t)bm*DH + d] = __float2bfloat16(sq * QSCALE);
    klb[(size_t)bm*DH + d] = __float2bfloat16(sk * QSCALE);
}

// ---------------- softmaxes ---------------------------------------------------------
__global__ void softmax_kernel(float* __restrict__ p, int cols)
{
    extern __shared__ float buf[];
    __shared__ float red[32];
    float* x = p + (size_t)blockIdx.x * cols;
    int tid = threadIdx.x;
    float m = -1e30f;
    for (int c = tid; c < cols; c += blockDim.x) { float v = x[c]; buf[c] = v; m = fmaxf(m, v); }
    for (int o = 16; o; o >>= 1) m = fmaxf(m, __shfl_xor_sync(~0u, m, o));
    if ((tid & 31) == 0) red[tid >> 5] = m;
    __syncthreads();
    if (tid == 0) { float v = -1e30f; for (int i = 0; i < (int)blockDim.x/32; i++) v = fmaxf(v, red[i]); red[0] = v; }
    __syncthreads();
    m = red[0];
    float s = 0;
    for (int c = tid; c < cols; c += blockDim.x) { float e = expf(buf[c] - m); buf[c] = e; s += e; }
    __syncthreads();
    for (int o = 16; o; o >>= 1) s += __shfl_xor_sync(~0u, s, o);
    if ((tid & 31) == 0) red[tid >> 5] = s;
    __syncthreads();
    if (tid == 0) { float v = 0; for (int i = 0; i < (int)blockDim.x/32; i++) v += red[i]; red[0] = v; }
    __syncthreads();
    float inv = 1.f / red[0];
    for (int c = tid; c < cols; c += blockDim.x) x[c] = buf[c] * inv;
}

// bf16 in-place softmax
__global__ void softmax_b16io_kernel(__nv_bfloat16* __restrict__ p, int cols)
{
    extern __shared__ float buf[];
    __shared__ float red[32];
    __nv_bfloat16* x = p + (size_t)blockIdx.x * cols;
    int tid = threadIdx.x;
    float m = -1e30f;
    for (int c = tid; c < cols; c += blockDim.x) {
        float v = __bfloat162float(x[c]); buf[c] = v; m = fmaxf(m, v);
    }
    for (int o = 16; o; o >>= 1) m = fmaxf(m, __shfl_xor_sync(~0u, m, o));
    if ((tid & 31) == 0) red[tid >> 5] = m;
    __syncthreads();
    if (tid == 0) { float v = -1e30f; for (int i = 0; i < (int)blockDim.x/32; i++) v = fmaxf(v, red[i]); red[0] = v; }
    __syncthreads();
    m = red[0];
    float s = 0;
    for (int c = tid; c < cols; c += blockDim.x) { float e = expf(buf[c] - m); buf[c] = e; s += e; }
    __syncthreads();
    for (int o = 16; o; o >>= 1) s += __shfl_xor_sync(~0u, s, o);
    if ((tid & 31) == 0) red[tid >> 5] = s;
    __syncthreads();
    if (tid == 0) { float v = 0; for (int i = 0; i < (int)blockDim.x/32; i++) v += red[i]; red[0] = v; }
    __syncthreads();
    float inv = 1.f / red[0];
    for (int c = tid; c < cols; c += blockDim.x) x[c] = __float2bfloat16(buf[c] * inv);
}

// ---------------- depthwise conv: cv = conv(v) (fp32) ------------------------------
#define CTOK 64
__global__ void conv_kernel(const float* __restrict__ qkv, const float* __restrict__ wc,
                            float* __restrict__ cv)
{
    __shared__ float sv[CTOK + KSZ - 1][DH];
    __shared__ float swc[KSZ];
    const int b  = blockIdx.y;
    const int n0 = blockIdx.x * CTOK;
    const int tid = threadIdx.x;
    if (tid < KSZ) swc[tid] = wc[tid];
    const float* vb = qkv + (size_t)b * SEQ * QKVW + 128;
    const int half = KSZ / 2;
    for (int idx = tid; idx < (CTOK + KSZ - 1) * DH; idx += 256) {
        int r = idx / DH, d = idx % DH;
        int n = n0 - half + r;
        sv[r][d] = (n >= 0 && n < SEQ) ? vb[(size_t)n*QKVW + d] : 0.f;
    }
    __syncthreads();
    int d = tid % DH, tr = tid / DH;
    for (int t = tr; t < CTOK; t += 4) {
        float acc = 0;
#pragma unroll
        for (int j = 0; j < KSZ; j++) acc += sv[t + j][d] * swc[j];
        cv[((size_t)b*SEQ + n0 + t)*DH + d] = acc;
    }
}

__global__ void zero_kernel(float* p, int n)
{
    int i = blockIdx.x * 256 + threadIdx.x;
    if (i < n) p[i] = 0.f;
}

// ---------------- launcher --------------------------------------------------------
extern "C" void kernel_launch(void* const* d_in, const int* in_sizes, int n_in,
                              void* d_out, int out_size)
{
    static cudaStream_t s1 = nullptr, s2 = nullptr;
    static cudaEvent_t eL = nullptr, e1 = nullptr, e2 = nullptr, eLft = nullptr, e3 = nullptr;
    if (!s1) {
        cudaStreamCreateWithFlags(&s1, cudaStreamNonBlocking);
        cudaStreamCreateWithFlags(&s2, cudaStreamNonBlocking);
        cudaEventCreateWithFlags(&eL, cudaEventDisableTiming);
        cudaEventCreateWithFlags(&e1, cudaEventDisableTiming);
        cudaEventCreateWithFlags(&e2, cudaEventDisableTiming);
        cudaEventCreateWithFlags(&eLft, cudaEventDisableTiming);
        cudaEventCreateWithFlags(&e3, cudaEventDisableTiming);
    }

    const float* x      = (const float*)d_in[0];
    const float* gamma  = (const float*)d_in[1];
    const float* betap  = (const float*)d_in[2];
    const float* w_qkv  = (const float*)d_in[3];
    const float* w_out  = (const float*)d_in[4];
    const float* b_out  = (const float*)d_in[5];
    const float* w_conv = (const float*)d_in[6];

    float* y    = (float*)d_out;
    float* attn = (float*)d_out + (size_t)TOK * DIMF;

    float *qkv,*ql,*kl,*a2,*z,*a3v,*cv;
    __nv_bfloat16 *xnb,*wqkvTb,*woutTb,*qkvb,*qlb,*klb,*a1b,*zb,*leftb,*a3b,*a3vTb,*ohb;
    cudaGetSymbolAddress((void**)&qkv,  g_qkv);
    cudaGetSymbolAddress((void**)&ql,   g_ql);
    cudaGetSymbolAddress((void**)&kl,   g_kl);
    cudaGetSymbolAddress((void**)&a2,   g_a2);
    cudaGetSymbolAddress((void**)&z,    g_z);
    cudaGetSymbolAddress((void**)&a3v,  g_a3v);
    cudaGetSymbolAddress((void**)&cv,   g_cv);
    cudaGetSymbolAddress((void**)&xnb,  g_xnb);
    cudaGetSymbolAddress((void**)&wqkvTb, g_wqkvTb);
    cudaGetSymbolAddress((void**)&woutTb, g_woutTb);
    cudaGetSymbolAddress((void**)&qkvb, g_qkvb);
    cudaGetSymbolAddress((void**)&qlb,  g_qlb);
    cudaGetSymbolAddress((void**)&klb,  g_klb);
    cudaGetSymbolAddress((void**)&a1b,  g_a1b);
    cudaGetSymbolAddress((void**)&zb,   g_zb);
    cudaGetSymbolAddress((void**)&leftb,g_leftb);
    cudaGetSymbolAddress((void**)&a3b,  g_a3b);
    cudaGetSymbolAddress((void**)&a3vTb,g_a3vTb);
    cudaGetSymbolAddress((void**)&ohb,  g_ohb);

    const long long bsM = (long long)MLM*MLM;
    const float* v = qkv + 128;
    const __nv_bfloat16* qkb_q = qkvb;
    const __nv_bfloat16* qkb_k = qkvb + 64;

    // -------- main stream: spine --------
    ln_kernel<<<TOK, 256>>>(x, gamma, betap, xnb);
    tconv_kernel<<<dim3(QKVW/32, DIMF/32, 1), dim3(32,8)>>>(w_qkv, wqkvTb, DIMF, QKVW, 0, 0);
    tconv_kernel<<<dim3(DIMF/32, DH/32, 1), dim3(32,8)>>>(w_out, woutTb, DH, DIMF, 0, 0);
    {
        dim3 g(QKVW/64, TOK/128, 1);
        hgemm_tt<64,1,false><<<g, 256>>>(xnb, wqkvTb, qkv, qkvb, nullptr, nullptr,
            DIMF, DIMF, DIMF, QKVW, 0, 0, 0);
    }
    landmark_kernel<<<BATCH*MLM/4, 256>>>(qkv, ql, kl, qlb, klb);
    cudaEventRecord(eL, 0);

    // -------- branch 1: sim1 -> softmax(a1b) --------
    cudaStreamWaitEvent(s1, eL, 0);
    {
        dim3 g(MLM/128, SEQ/128, BATCH);
        hgemm_tt<128,2,false><<<g, 256, 0, s1>>>(qkb_q, klb, nullptr, a1b, nullptr, nullptr,
            DH, QKVW, DH, MLM, (long long)SEQ*QKVW, (long long)MLM*DH, (long long)SEQ*MLM);
    }
    softmax_b16io_kernel<<<BATCH*SEQ, 256, MLM*4, s1>>>(a1b, MLM);
    cudaEventRecord(e1, s1);

    // -------- branch 2: sim3 -> softmax(a3b) -> a3v -> a3vT ; conv --------
    cudaStreamWaitEvent(s2, eL, 0);
    {
        dim3 g(SEQ/128, MLM/128, BATCH);
        hgemm_tt<128,2,false><<<g, 256, 0, s2>>>(qlb, qkb_k, nullptr, a3b, nullptr, nullptr,
            DH, DH, QKVW, SEQ, (long long)MLM*DH, (long long)SEQ*QKVW, (long long)MLM*SEQ);
    }
    softmax_b16io_kernel<<<BATCH*MLM, 256, SEQ*4, s2>>>(a3b, SEQ);
    zero_kernel<<<(BATCH*MLM*DH + 255)/256, 256, 0, s2>>>(a3v, BATCH*MLM*DH);
    {
        dim3 g(DH/64, (MLM/64)*32, BATCH);
        sgemm_k<64,64,16,4,4,true><<<g, 256, 0, s2>>>(a3b, v, nullptr, nullptr, a3v,
            MLM, DH, SEQ, SEQ, QKVW, DH,
            (long long)MLM*SEQ, (long long)SEQ*QKVW, 0, (long long)MLM*DH, 1.f, 0.f, 0, 32);
    }
    tconv_kernel<<<dim3(DH/32, MLM/32, BATCH), dim3(32,8), 0, s2>>>(a3v, a3vTb, MLM, DH,
        (long long)MLM*DH, (long long)MLM*DH);
    conv_kernel<<<dim3(SEQ/CTOK, BATCH), 256, 0, s2>>>(qkv, w_conv, cv);
    cudaEventRecord(e2, s2);

    // -------- spine continues: sim2 -> softmax -> pinv --------
    {
        dim3 g(MLM/32, MLM/32, BATCH);
        sgemm_k<32,32,32,2,2,false><<<g, 256>>>(ql, kl, nullptr, nullptr, a2,
            MLM, MLM, DH, DH, DH, MLM,
            (long long)MLM*DH, (long long)MLM*DH, 0, bsM, QSCALE, 0.f, 1, 1);
    }
    softmax_kernel<<<BATCH*MLM, 256, MLM*4>>>(a2, MLM);
    zero_bar_kernel<<<1, 32>>>();
    pinv_fused<<<PINV_CTAS, 128>>>();     // result in g_z
    f2bf_kernel<<<(BATCH*MLM*MLM/4 + 255)/256, 256>>>(z, zb, BATCH*MLM*MLM/4);

    // -------- join: left needs a1b --------
    cudaStreamWaitEvent(0, e1, 0);
    {
        dim3 g(MLM/128, SEQ/128, BATCH);
        hgemm_tt<128,2,true><<<g, 256>>>(a1b, zb, nullptr, leftb, nullptr, nullptr,
            MLM, MLM, MLM, MLM, (long long)SEQ*MLM, bsM, (long long)SEQ*MLM);
    }
    cudaEventRecord(eLft, 0);

    // -------- side stream: oh + projection (overlaps attn) --------
    cudaStreamWaitEvent(s1, eLft, 0);
    cudaStreamWaitEvent(s1, e2, 0);
    {
        dim3 g(1, SEQ/128, BATCH);
        hgemm_tt<64,4,false><<<g, 256, 0, s1>>>(leftb, a3vTb, nullptr, ohb, cv, nullptr,
            MLM, MLM, MLM, DH, (long long)SEQ*MLM, (long long)DH*MLM, (long long)SEQ*DH);
    }
    {
        dim3 g(DIMF/128, TOK/128, 1);
        hgemm_tt<128,3,false><<<g, 256, 0, s1>>>(ohb, woutTb, y, nullptr, x, b_out,
            DH, DH, DH, DIMF, 0, 0, 0);
    }
    cudaEventRecord(e3, s1);

    // -------- main stream: attn = leftb @ a3b (proven 128x128 tile) --------
    {
        dim3 g(SEQ/128, SEQ/128, BATCH);
        hgemm_tt<128,0,true><<<g, 256>>>(leftb, a3b, attn, nullptr, nullptr, nullptr,
            MLM, MLM, SEQ, SEQ, (long long)SEQ*MLM, (long long)MLM*SEQ, (long long)SEQ*SEQ);
    }
    cudaStreamWaitEvent(0, e3, 0);
}